// round 2
// baseline (speedup 1.0000x reference)
#include <cuda_runtime.h>
#include <cuda_bf16.h>

#define LEN_M   131328
#define D_H     256
#define N_MC    64
#define DDP1    513       // DATA_DIM_P1 (K)
#define NROWS   4096      // N (GEMM M)
#define NCOL    512       // 2*D_H  (GEMM N: [A|B])
#define KTILES  33        // ceil(513/16)

// Scratch (no allocations allowed): packed weights [m|s] and GEMM result [A|B]
__device__ float g_W[DDP1 * NCOL];     // g_W[d*512 + c]
__device__ float g_C[NROWS * NCOL];    // g_C[n*512 + c]

// ---------------------------------------------------------------------------
// Kernel 1: build m, v, s; write m_w0 / v_w0 outputs; pack W = [m | s]
// ---------------------------------------------------------------------------
__global__ void prep_kernel(const float* __restrict__ params,
                            float* __restrict__ out_m,
                            float* __restrict__ out_v) {
    int i = blockIdx.x * blockDim.x + threadIdx.x;
    if (i >= LEN_M) return;
    float m = params[i];
    float v = fmaxf(params[LEN_M + i], 0.0f) + 1e-6f;
    float s = sqrtf(v);
    out_m[i] = m;
    out_v[i] = v;
    int d = i >> 8;        // i / 256
    int h = i & 255;       // i % 256
    g_W[d * NCOL + h]        = m;
    g_W[d * NCOL + D_H + h]  = s;
}

// ---------------------------------------------------------------------------
// Kernel 2: C[4096,512] = x[4096,513] @ W[513,512]   (fp32, packed f32x2 FMA)
// Block tile 128x128, BK=16, 256 threads, thread tile 8x8 (4 row-pairs x 8 cols)
// ---------------------------------------------------------------------------
#define XS_STRIDE 130               // pad: conflict-free STS (stride-130 banks)
#define WS_STRIDE 136               // 128 + 2-per-32 pad: conflict-free strided LDS

__device__ __forceinline__ int wphys(int c) { return c + ((c >> 5) << 1); }

#define FMA2(acc, a, b) \
    asm("fma.rn.f32x2 %0, %1, %2, %0;" : "+l"(acc) : "l"(a), "l"(b))

__global__ __launch_bounds__(256, 1)
void gemm_kernel(const float* __restrict__ x) {
    __shared__ __align__(16) float xs[2][16][XS_STRIDE]; // xs[buf][k][row]
    __shared__ __align__(16) float ws[2][16][WS_STRIDE]; // ws[buf][k][col(phys)]

    const int tid  = threadIdx.x;
    const int trid = tid >> 4;   // 0..15 row group (8 rows each)
    const int tcid = tid & 15;   // 0..15 col group (8 cols each)
    const int rowBase = blockIdx.y * 128;
    const int colBase = blockIdx.x * 128;

    unsigned long long acc[4][8];
    #pragma unroll
    for (int j = 0; j < 4; j++)
        #pragma unroll
        for (int c = 0; c < 8; c++)
            acc[j][c] = 0ull;

    float xreg[8], wreg[8];

    auto ldg_tile = [&](int t) {
        #pragma unroll
        for (int i = 0; i < 8; i++) {          // x tile: 128 rows x 16 k
            int e  = tid + i * 256;
            int kk = e & 15, rr = e >> 4;
            int col = t * 16 + kk;
            xreg[i] = (col < DDP1) ? x[(rowBase + rr) * DDP1 + col] : 0.0f;
        }
        #pragma unroll
        for (int i = 0; i < 8; i++) {          // w tile: 16 k x 128 cols
            int e  = tid + i * 256;
            int kk = e >> 7, cc = e & 127;
            int row = t * 16 + kk;
            wreg[i] = (row < DDP1) ? g_W[row * NCOL + colBase + cc] : 0.0f;
        }
    };
    auto sts_tile = [&](int buf) {
        #pragma unroll
        for (int i = 0; i < 8; i++) {
            int e = tid + i * 256;
            xs[buf][e & 15][e >> 4] = xreg[i];
        }
        #pragma unroll
        for (int i = 0; i < 8; i++) {
            int e = tid + i * 256;
            ws[buf][e >> 7][wphys(e & 127)] = wreg[i];
        }
    };

    ldg_tile(0);
    sts_tile(0);
    __syncthreads();

    for (int t = 0; t < KTILES; t++) {
        int buf = t & 1;
        if (t + 1 < KTILES) ldg_tile(t + 1);   // register-staged prefetch

        #pragma unroll
        for (int kk = 0; kk < 16; kk++) {
            unsigned long long a[4], w2[8];
            #pragma unroll
            for (int j = 0; j < 4; j++)        // row pairs (8B-aligned LDS.64)
                a[j] = *(const unsigned long long*)&xs[buf][kk][trid * 8 + 2 * j];
            #pragma unroll
            for (int j = 0; j < 4; j++) {      // cols, duplicated into both f32x2 lanes
                float2 wv = *(const float2*)&ws[buf][kk][wphys(tcid * 8 + 2 * j)];
                unsigned int bx = __float_as_uint(wv.x);
                unsigned int by = __float_as_uint(wv.y);
                w2[2 * j]     = ((unsigned long long)bx << 32) | bx;
                w2[2 * j + 1] = ((unsigned long long)by << 32) | by;
            }
            #pragma unroll
            for (int c = 0; c < 8; c++)
                #pragma unroll
                for (int j = 0; j < 4; j++)
                    FMA2(acc[j][c], a[j], w2[c]);
        }

        if (t + 1 < KTILES) {
            __syncthreads();                   // all reads of buf^1 (iter t-1) done
            sts_tile(buf ^ 1);
            __syncthreads();
        }
    }

    #pragma unroll
    for (int j = 0; j < 4; j++) {
        int r0 = rowBase + trid * 8 + 2 * j;
        #pragma unroll
        for (int c = 0; c < 8; c++) {
            float2 v = *(float2*)&acc[j][c];
            int col = colBase + tcid * 8 + c;
            g_C[r0 * NCOL + col]       = v.x;
            g_C[(r0 + 1) * NCOL + col] = v.y;
        }
    }
}

// ---------------------------------------------------------------------------
// Kernel 3: pred[n,mc] = W1[0] + sum_h relu(A[n,h] + eps[mc]*B[n,h]) * W1[h+1]
// Block: 4 rows n x 64 mc = 256 threads
// ---------------------------------------------------------------------------
__global__ __launch_bounds__(256)
void epi_kernel(const float* __restrict__ W1,
                const float* __restrict__ eps,
                float* __restrict__ out_pred) {
    __shared__ float sAB[4][512];
    __shared__ float sW1[257];

    int tid = threadIdx.x;
    int rg  = tid >> 6;         // row within block (0..3)
    int mc  = tid & 63;         // MC sample
    int n   = blockIdx.x * 4 + rg;

    #pragma unroll
    for (int i = 0; i < 8; i++)
        sAB[rg][mc + i * 64] = g_C[n * NCOL + mc + i * 64];
    // FIX (R1 bug): cover ALL 257 W1 elements. Previous `if (tid < 257)` with
    // 256 threads left sW1[256] holding stale smem from the prior kernel.
    for (int i = tid; i < 257; i += 256) sW1[i] = W1[i];
    __syncthreads();

    float e   = eps[mc];
    float acc = sW1[0];
    const float* A = sAB[rg];
    const float* B = sAB[rg] + 256;

    #pragma unroll 8
    for (int h = 0; h < 256; h++) {
        float t = fmaf(e, B[h], A[h]);
        t = fmaxf(t, 0.0f);
        acc = fmaf(t, sW1[h + 1], acc);
    }

    out_pred[n * N_MC + mc] = acc;
}

// ---------------------------------------------------------------------------
extern "C" void kernel_launch(void* const* d_in, const int* in_sizes, int n_in,
                              void* d_out, int out_size) {
    const float* params = (const float*)d_in[0];   // 2*LEN_M
    const float* W1     = (const float*)d_in[1];   // 257
    const float* x      = (const float*)d_in[2];   // 4096*513
    const float* eps    = (const float*)d_in[3];   // 64

    float* out      = (float*)d_out;
    float* out_pred = out;                          // 4096*64
    float* out_m    = out + NROWS * N_MC;           // 131328
    float* out_v    = out_m + LEN_M;                // 131328

    prep_kernel<<<(LEN_M + 255) / 256, 256>>>(params, out_m, out_v);

    dim3 grid(NCOL / 128, NROWS / 128);             // 4 x 32 = 128 blocks
    gemm_kernel<<<grid, 256>>>(x);

    epi_kernel<<<NROWS / 4, 256>>>(W1, eps, out_pred);
}

// round 4
// speedup vs baseline: 2.1097x; 2.1097x over previous
#include <cuda_runtime.h>
#include <cuda_bf16.h>
#include <cstdint>

#define LEN_M   131328
#define D_H     256
#define N_MC    64
#define DDP1    513
#define NROWS   4096
#define NCOL    512        // 2*D_H : C = [A|B] = [x@m | x@s]
#define KP      512        // MMA K (col 512 handled as rank-1 update)
#define NCHUNK  8          // 512 / 64
#define BKB     128        // bytes per smem row (64 bf16) = SW128 atom

// -------- persistent scratch (no allocs allowed) ---------------------------
__device__ __align__(128) __nv_bfloat16 g_xh[NROWS * KP];
__device__ __align__(128) __nv_bfloat16 g_xl[NROWS * KP];
__device__ __align__(128) __nv_bfloat16 g_bh[NCOL * KP];   // B[n][k] = W[k][n]
__device__ __align__(128) __nv_bfloat16 g_bl[NCOL * KP];
__device__ __align__(128) float g_x512[NROWS];
__device__ __align__(128) float g_w512[NCOL];
__device__ __align__(128) float g_C[NROWS * NCOL];

// -------- PTX helpers (arch-neutral: LDSM / HMMA / LDGSTS only) ------------
__device__ __forceinline__ uint32_t s2u(const void* p) {
    uint32_t a;
    asm("{ .reg .u64 t; cvta.to.shared.u64 t, %1; cvt.u32.u64 %0, t; }"
        : "=r"(a) : "l"(p));
    return a;
}
#define SW128(o) ((o) ^ (((o) >> 3) & 0x70))

#define LDSM_X4(r, a)                                                         \
    asm volatile("ldmatrix.sync.aligned.m8n8.x4.shared.b16 {%0,%1,%2,%3}, [%4];" \
        : "=r"((r)[0]), "=r"((r)[1]), "=r"((r)[2]), "=r"((r)[3]) : "r"(a))

#define MMA16816(d, a, b)                                                     \
    asm volatile("mma.sync.aligned.m16n8k16.row.col.f32.bf16.bf16.f32 "       \
        "{%0,%1,%2,%3}, {%4,%5,%6,%7}, {%8,%9}, {%0,%1,%2,%3};"               \
        : "+f"((d)[0]), "+f"((d)[1]), "+f"((d)[2]), "+f"((d)[3])              \
        : "r"((a)[0]), "r"((a)[1]), "r"((a)[2]), "r"((a)[3]),                 \
          "r"((b)[0]), "r"((b)[1]))

// -------- Kernel 1a: weights -> outputs + bf16 split, transposed -----------
__global__ void prep_w(const float* __restrict__ params,
                       float* __restrict__ out_m, float* __restrict__ out_v) {
    int idx = blockIdx.x * blockDim.x + threadIdx.x;
    if (idx >= NCOL * DDP1) return;
    int c = idx / DDP1;
    int d = idx - c * DDP1;
    int h = c & 255;
    int i = d * 256 + h;
    float w;
    if (c < 256) {
        float m = params[i];
        out_m[i] = m;
        w = m;
    } else {
        float v = fmaxf(params[LEN_M + i], 0.0f) + 1e-6f;
        out_v[i] = v;
        w = sqrtf(v);
    }
    if (d == 512) { g_w512[c] = w; return; }
    __nv_bfloat16 hi = __float2bfloat16(w);
    __nv_bfloat16 lo = __float2bfloat16(w - __bfloat162float(hi));
    g_bh[c * KP + d] = hi;
    g_bl[c * KP + d] = lo;
}

// -------- Kernel 1b: x -> bf16 split ----------------------------------------
__global__ void prep_x(const float* __restrict__ x) {
    int idx = blockIdx.x * blockDim.x + threadIdx.x;
    if (idx >= NROWS * DDP1) return;
    int n = idx / DDP1;
    int k = idx - n * DDP1;
    float v = x[idx];
    if (k == 512) { g_x512[n] = v; return; }
    __nv_bfloat16 hi = __float2bfloat16(v);
    __nv_bfloat16 lo = __float2bfloat16(v - __bfloat162float(hi));
    g_xh[n * KP + k] = hi;
    g_xl[n * KP + k] = lo;
}

// -------- Kernel 2: HMMA GEMM  C[4096,512] = x @ W  (bf16x3) ----------------
// grid (4, 32): block tile 128(M) x 128(N), 8 warps as 2(M)x4(N) -> 64x32/warp
// K = 8 chunks of 64 bf16 (128B SW128 rows), cp.async double-buffered.
#define TILE_B   16384                  // one 128x64 bf16 tile
#define CHSET_B  (4 * TILE_B)           // Ah | Al | Bh | Bl
#define GSMEM    (1024 + 2 * CHSET_B)   // sw512 + 2 buffers

__global__ __launch_bounds__(256, 1) void gemm_mma() {
    extern __shared__ __align__(1024) char smem[];
    const uint32_t sb = s2u(smem);
    float* sw512 = (float*)smem;          // 128 floats: W[512, colBase..+127]
    const uint32_t TB = sb + 1024;

    const int tid  = threadIdx.x;
    const int lane = tid & 31;
    const int warp = tid >> 5;
    const int wm = warp >> 2;             // 0..1  (M half, 64 rows)
    const int wn = warp & 3;              // 0..3  (N quarter, 32 cols)
    const int rowBase = blockIdx.y * 128;
    const int colBase = blockIdx.x * 128;

    if (tid < 128) sw512[tid] = g_w512[colBase + tid];

    float acc[4][4][4];
    #pragma unroll
    for (int mi = 0; mi < 4; mi++)
        #pragma unroll
        for (int nj = 0; nj < 4; nj++)
            #pragma unroll
            for (int q = 0; q < 4; q++)
                acc[mi][nj][q] = 0.0f;

    // issue one K-chunk (c) of all 4 tiles into buffer `buf` via cp.async
    auto issue_chunk = [&](int c, int buf) {
        const uint32_t tb = TB + buf * CHSET_B;
        #pragma unroll
        for (int t = 0; t < 4; t++) {
            const char* gbase = (t == 0) ? (const char*)g_xh
                              : (t == 1) ? (const char*)g_xl
                              : (t == 2) ? (const char*)g_bh
                                         : (const char*)g_bl;
            const int rbase = (t < 2) ? rowBase : colBase;
            #pragma unroll
            for (int i = 0; i < 4; i++) {
                int q = tid + i * 256;        // 0..1023 : 128 rows x 8 16B-slots
                int r = q >> 3, s = q & 7;
                const char* gp = gbase + (size_t)(rbase + r) * (KP * 2)
                               + c * BKB + s * 16;
                uint32_t sp = tb + t * TILE_B + SW128(r * BKB + s * 16);
                asm volatile("cp.async.cg.shared.global [%0], [%1], 16;"
                             :: "r"(sp), "l"(gp));
            }
        }
        asm volatile("cp.async.commit_group;" ::: "memory");
    };

    issue_chunk(0, 0);

    for (int c = 0; c < NCHUNK; c++) {
        const int buf = c & 1;
        if (c + 1 < NCHUNK) {
            issue_chunk(c + 1, buf ^ 1);
            asm volatile("cp.async.wait_group 1;" ::: "memory");
        } else {
            asm volatile("cp.async.wait_group 0;" ::: "memory");
        }
        __syncthreads();

        const uint32_t Ah = TB + buf * CHSET_B;
        const uint32_t Al = Ah + TILE_B;
        const uint32_t Bh = Al + TILE_B;
        const uint32_t Bl = Bh + TILE_B;

        #pragma unroll
        for (int s = 0; s < 4; s++) {        // four k16 steps per chunk
            const int k0 = s * 16;
            uint32_t ah[4][4], al[4][4], bhf[4][2], blf[4][2];

            #pragma unroll
            for (int mi = 0; mi < 4; mi++) {  // A frags: 16x16 per ldmatrix.x4
                int row = wm * 64 + mi * 16 + (lane & 15);
                int col = k0 + ((lane >> 4) << 3);
                uint32_t off = SW128(row * BKB + col * 2);
                LDSM_X4(ah[mi], Ah + off);
                LDSM_X4(al[mi], Al + off);
            }
            #pragma unroll
            for (int p = 0; p < 2; p++) {     // B frags: n16xk16 per ldmatrix.x4
                int row = wn * 32 + p * 16 + (lane & 7) + ((lane & 16) >> 1);
                int col = k0 + (lane & 8);
                uint32_t off = SW128(row * BKB + col * 2);
                uint32_t r[4];
                LDSM_X4(r, Bh + off);
                bhf[p * 2][0] = r[0]; bhf[p * 2][1] = r[1];
                bhf[p * 2 + 1][0] = r[2]; bhf[p * 2 + 1][1] = r[3];
                LDSM_X4(r, Bl + off);
                blf[p * 2][0] = r[0]; blf[p * 2][1] = r[1];
                blf[p * 2 + 1][0] = r[2]; blf[p * 2 + 1][1] = r[3];
            }

            #pragma unroll
            for (int mi = 0; mi < 4; mi++)
                #pragma unroll
                for (int nj = 0; nj < 4; nj++) {
                    MMA16816(acc[mi][nj], ah[mi], bhf[nj]);   // xh*wh
                    MMA16816(acc[mi][nj], ah[mi], blf[nj]);   // xh*wl
                    MMA16816(acc[mi][nj], al[mi], bhf[nj]);   // xl*wh
                }
        }
        __syncthreads();                     // done reading buf before reuse
    }

    // epilogue: rank-1 update (K column 512) + store fp32
    #pragma unroll
    for (int mi = 0; mi < 4; mi++) {
        int r0 = rowBase + wm * 64 + mi * 16 + (lane >> 2);
        float xv0 = g_x512[r0];
        float xv1 = g_x512[r0 + 8];
        #pragma unroll
        for (int nj = 0; nj < 4; nj++) {
            int cl = wn * 32 + nj * 8 + ((lane & 3) << 1);
            float w0 = sw512[cl], w1 = sw512[cl + 1];
            float2 v0 = { acc[mi][nj][0] + xv0 * w0, acc[mi][nj][1] + xv0 * w1 };
            float2 v1 = { acc[mi][nj][2] + xv1 * w0, acc[mi][nj][3] + xv1 * w1 };
            *(float2*)&g_C[(size_t)r0 * NCOL + colBase + cl]       = v0;
            *(float2*)&g_C[(size_t)(r0 + 8) * NCOL + colBase + cl] = v1;
        }
    }
}

// -------- Kernel 3: epilogue  pred[n,mc] -----------------------------------
typedef unsigned long long ull;
__device__ __forceinline__ ull pk2(float x, float y) {
    ull r; asm("mov.b64 %0, {%1,%2};" : "=l"(r) : "f"(x), "f"(y)); return r;
}
__device__ __forceinline__ float2 upk2(ull v) {
    float2 r; asm("mov.b64 {%0,%1}, %2;" : "=f"(r.x), "=f"(r.y) : "l"(v)); return r;
}
__device__ __forceinline__ ull fma2(ull a, ull b, ull c) {
    ull r; asm("fma.rn.f32x2 %0, %1, %2, %3;" : "=l"(r) : "l"(a), "l"(b), "l"(c));
    return r;
}

__global__ __launch_bounds__(128) void epi_kernel(const float* __restrict__ W1,
                                                  const float* __restrict__ eps,
                                                  float* __restrict__ out_pred) {
    __shared__ float sAB[4][512];
    __shared__ float sW[256];     // W1[h+1]
    __shared__ float sw0;

    const int tid = threadIdx.x, rg = tid >> 5, lane = tid & 31;
    const int n = blockIdx.x * 4 + rg;

    const float4* src = (const float4*)&g_C[(size_t)n * NCOL];
    float4* dst = (float4*)sAB[rg];
    #pragma unroll
    for (int i = 0; i < 4; i++) dst[lane + i * 32] = src[lane + i * 32];
    for (int i = tid; i < 256; i += 128) sW[i] = W1[i + 1];
    if (tid == 0) sw0 = W1[0];
    __syncthreads();

    const ull e2 = pk2(eps[2 * lane], eps[2 * lane + 1]);
    ull acc = pk2(sw0, sw0);

    const float4* A4 = (const float4*)&sAB[rg][0];
    const float4* B4 = (const float4*)&sAB[rg][256];
    const float4* W4 = (const float4*)sW;

    #pragma unroll 4
    for (int h4 = 0; h4 < 64; h4++) {
        float4 a = A4[h4], b = B4[h4], w = W4[h4];
        {
            ull t = fma2(e2, pk2(b.x, b.x), pk2(a.x, a.x));
            float2 tv = upk2(t);
            tv.x = fmaxf(tv.x, 0.0f); tv.y = fmaxf(tv.y, 0.0f);
            acc = fma2(pk2(tv.x, tv.y), pk2(w.x, w.x), acc);
        }
        {
            ull t = fma2(e2, pk2(b.y, b.y), pk2(a.y, a.y));
            float2 tv = upk2(t);
            tv.x = fmaxf(tv.x, 0.0f); tv.y = fmaxf(tv.y, 0.0f);
            acc = fma2(pk2(tv.x, tv.y), pk2(w.y, w.y), acc);
        }
        {
            ull t = fma2(e2, pk2(b.z, b.z), pk2(a.z, a.z));
            float2 tv = upk2(t);
            tv.x = fmaxf(tv.x, 0.0f); tv.y = fmaxf(tv.y, 0.0f);
            acc = fma2(pk2(tv.x, tv.y), pk2(w.z, w.z), acc);
        }
        {
            ull t = fma2(e2, pk2(b.w, b.w), pk2(a.w, a.w));
            float2 tv = upk2(t);
            tv.x = fmaxf(tv.x, 0.0f); tv.y = fmaxf(tv.y, 0.0f);
            acc = fma2(pk2(tv.x, tv.y), pk2(w.w, w.w), acc);
        }
    }

    float2 r = upk2(acc);
    ((float2*)out_pred)[n * 32 + lane] = r;
}

// ---------------------------------------------------------------------------
extern "C" void kernel_launch(void* const* d_in, const int* in_sizes, int n_in,
                              void* d_out, int out_size) {
    const float* params = (const float*)d_in[0];
    const float* W1     = (const float*)d_in[1];
    const float* x      = (const float*)d_in[2];
    const float* eps    = (const float*)d_in[3];

    float* out      = (float*)d_out;
    float* out_pred = out;
    float* out_m    = out + NROWS * N_MC;
    float* out_v    = out_m + LEN_M;

    cudaFuncSetAttribute(gemm_mma, cudaFuncAttributeMaxDynamicSharedMemorySize, GSMEM);

    prep_w<<<(NCOL * DDP1 + 255) / 256, 256>>>(params, out_m, out_v);
    prep_x<<<(NROWS * DDP1 + 255) / 256, 256>>>(x);
    gemm_mma<<<dim3(4, 32), 256, GSMEM>>>();
    epi_kernel<<<NROWS / 4, 128>>>(W1, eps, out_pred);
}